// round 10
// baseline (speedup 1.0000x reference)
#include <cuda_runtime.h>
#include <math.h>

#define NIN 14
#define HID 128
#define LAT 64
#define CBN 512
#define MAXN 131072
#define TB 128   /* tokens per k_vq batch */

#define SQRT2_F 1.41421356237f

// ---------------- device scratch (static: no allocations allowed) ----------------
__device__ unsigned long long g_zbuf[(size_t)MAXN * 32];  // z as f32x2 pairs, 33.5MB
__device__ float g_table[CBN * 16];                       // precomputed decoder outputs
__device__ float g_cbnorm[CBN];                           // sum(c*c), XLA:GPU warp-tree order
__device__ int g_hist[CBN];
__device__ unsigned long long g_commit;                   // fixed-point sum of ||q-z||^2

// ---------------- packed f32x2 helpers ----------------
static __device__ __forceinline__ unsigned long long ffma2(unsigned long long a,
                                                           unsigned long long b,
                                                           unsigned long long c) {
    unsigned long long d;
    asm("fma.rn.f32x2 %0, %1, %2, %3;" : "=l"(d) : "l"(a), "l"(b), "l"(c));
    return d;
}
static __device__ __forceinline__ unsigned long long fadd2(unsigned long long a,
                                                           unsigned long long b) {
    unsigned long long d;
    asm("add.rn.f32x2 %0, %1, %2;" : "=l"(d) : "l"(a), "l"(b));
    return d;
}
static __device__ __forceinline__ unsigned long long pack2(float lo, float hi) {
    unsigned long long r;
    asm("mov.b64 %0, {%1, %2};" : "=l"(r) : "r"(__float_as_uint(lo)), "r"(__float_as_uint(hi)));
    return r;
}
static __device__ __forceinline__ float2 unpack2(unsigned long long v) {
    unsigned int lo, hi;
    asm("mov.b64 {%0, %1}, %2;" : "=r"(lo), "=r"(hi) : "l"(v));
    float2 r;
    r.x = __uint_as_float(lo);
    r.y = __uint_as_float(hi);
    return r;
}

// reference-style GELU: 0.5 * x * (1 + erf(x / sqrt(2)))
static __device__ __forceinline__ float gelu_ref(float v) {
    float e = erff(v / SQRT2_F);
    return (v * (e + 1.f)) * 0.5f;
}

// XLA:GPU row-reduction emulation for 64-wide sum-of-squares (bit-frozen from R7).
#define GPU_SUMSQ64(getv, result) do {                                        \
    float _a[32];                                                             \
    _Pragma("unroll") for (int _t = 0; _t < 32; _t++) {                       \
        float _v0 = getv(_t);                                                 \
        float _v1 = getv(_t + 32);                                            \
        _a[_t] = fmaf(_v1, _v1, _v0 * _v0);                                   \
    }                                                                         \
    _Pragma("unroll") for (int _o = 16; _o >= 1; _o >>= 1)                    \
    _Pragma("unroll") for (int _t = 0; _t < 16; _t++)                         \
        if (_t < _o) _a[_t] = _a[_t] + _a[_t + _o];                           \
    result = _a[0];                                                           \
} while (0)

// ---------------- kernel 0: zero the cross-launch scratch ----------------
__global__ void k_init() {
    int t = threadIdx.x;
    if (t < CBN) g_hist[t] = 0;
    if (t == 0) g_commit = 0ULL;
}

// ---------------- kernel 1: decoder table (unchanged, bit-frozen) ----------
__global__ __launch_bounds__(256) void k_dectab(
    const float* __restrict__ cb,
    const float* __restrict__ w1, const float* __restrict__ b1,
    const float* __restrict__ g1, const float* __restrict__ bt1,
    const float* __restrict__ w2, const float* __restrict__ b2)
{
    __shared__ float w1s[LAT * HID];
    __shared__ float w2s[HID * NIN];
    __shared__ float cbuf[8][LAT];
    __shared__ float gbuf[8][HID];
    int tid = threadIdx.x;
    for (int i = tid; i < LAT * HID; i += 256) w1s[i] = w1[i];
    for (int i = tid; i < HID * NIN; i += 256) w2s[i] = w2[i];
    __syncthreads();

    int lane = tid & 31, w = tid >> 5;
    int c = blockIdx.x * 8 + w;

    for (int d = lane; d < LAT; d += 32) cbuf[w][d] = __ldg(&cb[c * LAT + d]);
    __syncwarp();

    if (lane == 0) {
        float ns;
#define GETC(d) (cbuf[w][(d)])
        GPU_SUMSQ64(GETC, ns);
#undef GETC
        g_cbnorm[c] = ns;
    }

    float h[4];
#pragma unroll
    for (int u = 0; u < 4; u++) {
        int j = u * 32 + lane;
        float acc = 0.f;
        for (int d = 0; d < LAT; d++) acc = fmaf(cbuf[w][d], w1s[d * HID + j], acc);
        h[u] = acc + __ldg(&b1[j]);
    }
    float s = (h[0] + h[1]) + (h[2] + h[3]);
#pragma unroll
    for (int o = 16; o; o >>= 1) s += __shfl_xor_sync(~0u, s, o);
    float mean = s * (1.f / HID);
    float dv[4], s2 = 0.f;
#pragma unroll
    for (int u = 0; u < 4; u++) { dv[u] = h[u] - mean; float sq = dv[u] * dv[u]; s2 = s2 + sq; }
#pragma unroll
    for (int o = 16; o; o >>= 1) s2 += __shfl_xor_sync(~0u, s2, o);
    float var = s2 * (1.f / HID);
    float rstd = 1.f / sqrtf(var + 1e-5f);
#pragma unroll
    for (int u = 0; u < 4; u++) {
        int j = u * 32 + lane;
        float t = dv[u] * rstd;
        float t2 = t * __ldg(&g1[j]);
        float v = t2 + __ldg(&bt1[j]);
        gbuf[w][j] = gelu_ref(v);
    }
    __syncwarp();
    if (lane < NIN) {
        float acc = 0.f;
        for (int j = 0; j < HID; j++) acc = fmaf(gbuf[w][j], w2s[j * NIN + lane], acc);
        g_table[c * 16 + lane] = acc + __ldg(&b2[lane]);
    }
}

// ---------------- kernel 2: encoder (unchanged from R9) ----------------------
__global__ __launch_bounds__(256) void k_enc(
    const float* __restrict__ x,
    const float* __restrict__ w1, const float* __restrict__ b1,
    const float* __restrict__ g1, const float* __restrict__ bt1,
    const float* __restrict__ w2, const float* __restrict__ b2, int N)
{
    extern __shared__ float esm[];
    float* w1s = esm;
    float* w2s = w1s + NIN * HID;
    unsigned long long* gsm = (unsigned long long*)(w2s + HID * LAT);

    int tid = threadIdx.x;
    for (int i = tid; i < NIN * HID; i += 256) w1s[i] = w1[i];
    for (int i = tid; i < HID * LAT; i += 256) w2s[i] = w2[i];
    __syncthreads();

    int lane = tid & 31, w = tid >> 5;

    float b1v[4], g1v[4], btv[4];
#pragma unroll
    for (int u = 0; u < 4; u++) {
        int j = u * 32 + lane;
        b1v[u] = __ldg(&b1[j]);
        g1v[u] = __ldg(&g1[j]);
        btv[u] = __ldg(&bt1[j]);
    }
    unsigned long long b2p = pack2(__ldg(&b2[2 * lane]), __ldg(&b2[2 * lane + 1]));

    int gw = blockIdx.x * 8 + w;
    int nw = gridDim.x * 8;

    for (int t0 = gw * 4; t0 < N; t0 += nw * 4) {
        float gl[4][4];
#pragma unroll
        for (int m = 0; m < 4; m++) {
            int t = t0 + m;
            if (t >= N) { gl[m][0] = gl[m][1] = gl[m][2] = gl[m][3] = 0.f; continue; }
            const float* xp = x + (size_t)t * NIN;
            float xv[NIN];
#pragma unroll
            for (int i = 0; i < NIN; i++) xv[i] = __ldg(&xp[i]);
            float h[4];
#pragma unroll
            for (int u = 0; u < 4; u++) {
                float acc = 0.f;
#pragma unroll
                for (int i = 0; i < NIN; i++) acc = fmaf(xv[i], w1s[i * HID + u * 32 + lane], acc);
                h[u] = acc + b1v[u];
            }
            float s = (h[0] + h[1]) + (h[2] + h[3]);
#pragma unroll
            for (int o = 16; o; o >>= 1) s += __shfl_xor_sync(~0u, s, o);
            float mean = s * (1.f / HID);
            float dv[4], s2 = 0.f;
#pragma unroll
            for (int u = 0; u < 4; u++) { dv[u] = h[u] - mean; float sq = dv[u] * dv[u]; s2 = s2 + sq; }
#pragma unroll
            for (int o = 16; o; o >>= 1) s2 += __shfl_xor_sync(~0u, s2, o);
            float var = s2 * (1.f / HID);
            float rstd = 1.f / sqrtf(var + 1e-5f);
#pragma unroll
            for (int u = 0; u < 4; u++) {
                float t1 = dv[u] * rstd;
                float t2 = t1 * g1v[u];
                float v = t2 + btv[u];
                gl[m][u] = gelu_ref(v);
            }
        }
#pragma unroll
        for (int m = 0; m < 4; m++)
#pragma unroll
            for (int u = 0; u < 4; u++) {
                unsigned long long gi = (unsigned long long)__float_as_uint(gl[m][u]);
                gsm[((w * 4 + m) * HID) + u * 32 + lane] = (gi << 32) | gi;
            }
        __syncwarp();
        unsigned long long acc0 = 0ULL, acc1 = 0ULL, acc2 = 0ULL, acc3 = 0ULL;
        const unsigned long long* g0p = gsm + (w * 4 + 0) * HID;
        const unsigned long long* g1p = gsm + (w * 4 + 1) * HID;
        const unsigned long long* g2p = gsm + (w * 4 + 2) * HID;
        const unsigned long long* g3p = gsm + (w * 4 + 3) * HID;
#pragma unroll 8
        for (int j = 0; j < HID; j++) {
            unsigned long long wj = *(const unsigned long long*)&w2s[j * LAT + 2 * lane];
            acc0 = ffma2(g0p[j], wj, acc0);
            acc1 = ffma2(g1p[j], wj, acc1);
            acc2 = ffma2(g2p[j], wj, acc2);
            acc3 = ffma2(g3p[j], wj, acc3);
        }
        __syncwarp();
        if (t0 + 0 < N) g_zbuf[(size_t)(t0 + 0) * 32 + lane] = fadd2(acc0, b2p);
        if (t0 + 1 < N) g_zbuf[(size_t)(t0 + 1) * 32 + lane] = fadd2(acc1, b2p);
        if (t0 + 2 < N) g_zbuf[(size_t)(t0 + 2) * 32 + lane] = fadd2(acc2, b2p);
        if (t0 + 3 < N) g_zbuf[(size_t)(t0 + 3) * 32 + lane] = fadd2(acc3, b2p);
    }
}

// ---------------- kernel 3: VQ — codebook in registers, z streamed via smem --
#define GZ_T(d) (((d) & 1) ? __uint_as_float((unsigned int)(z2t[(d) >> 1] >> 32)) \
                           : __uint_as_float((unsigned int)z2t[(d) >> 1]))

__global__ __launch_bounds__(512) void k_vq(
    const float* __restrict__ cb,
    float* __restrict__ out_rec, float* __restrict__ out_idx, int N)
{
    extern __shared__ unsigned long long sm_u[];
    unsigned long long* zb = sm_u;                        // TB*32 ull = 32KB
    float* wbb  = (float*)(zb + TB * 32);                 // [TB][16] warp-winner best
    float* wbb2 = wbb + TB * 16;                          // [TB][16] warp-winner best2
    int*   wbi  = (int*)(wbb2 + TB * 16);                 // [TB][16] warp-winner idx
    int*   hs   = wbi + TB * 16;                          // [CBN]
    __shared__ unsigned long long csum;

    int tid = threadIdx.x;
    int lane = tid & 31, w = tid >> 5;
    int c = w * 32 + lane;                                // this thread's code

    // load my codebook row into registers (32 packed ull), plus its screen norm
    unsigned long long creg[32];
    {
        const ulonglong2* crow = (const ulonglong2*)(cb + c * LAT);
#pragma unroll
        for (int u = 0; u < 16; u++) {
            ulonglong2 v = __ldg(&crow[u]);
            creg[2 * u] = v.x;
            creg[2 * u + 1] = v.y;
        }
    }
    float ccn = __ldg(&g_cbnorm[c]);

    hs[tid] = 0;
    if (tid == 0) csum = 0ULL;
    __syncthreads();

    for (int base = blockIdx.x * TB; base < N; base += gridDim.x * TB) {
        // ---- stage this batch's z into smem (coalesced; zero-pad tail) ----
        {
            size_t g0 = (size_t)base * 32;
            size_t gend = (size_t)N * 32;
            for (int i = tid; i < TB * 32; i += 512) {
                size_t gi = g0 + i;
                zb[i] = (gi < gend) ? g_zbuf[gi] : 0ULL;
            }
        }
        __syncthreads();

        // ---- compute phase: every warp scores its 32 codes against all TB tokens --
#pragma unroll 2
        for (int tok = 0; tok < TB; tok++) {
            const ulonglong2* zp = (const ulonglong2*)(zb + tok * 32);
            unsigned long long a0 = 0ULL, a1 = 0ULL;
#pragma unroll
            for (int u = 0; u < 8; u++) {
                ulonglong2 p = zp[2 * u];
                ulonglong2 q = zp[2 * u + 1];
                a0 = ffma2(p.x, creg[4 * u + 0], a0);
                a1 = ffma2(p.y, creg[4 * u + 1], a1);
                a0 = ffma2(q.x, creg[4 * u + 2], a0);
                a1 = ffma2(q.y, creg[4 * u + 3], a1);
            }
            float2 f = unpack2(fadd2(a0, a1));
            float b = fmaf(-2.f, f.x + f.y, ccn);
            float b2 = 3.4e38f;
            int bi = c;
            // warp top-2 argmin (first-index-wins on exact ties)
#pragma unroll
            for (int off = 16; off; off >>= 1) {
                float ob  = __shfl_xor_sync(~0u, b, off);
                float ob2 = __shfl_xor_sync(~0u, b2, off);
                int   oi  = __shfl_xor_sync(~0u, bi, off);
                if (ob < b || (ob == b && oi < bi)) {
                    b2 = fminf(b, ob2);
                    b = ob;
                    bi = oi;
                } else {
                    b2 = fminf(b2, ob);
                }
            }
            if (lane == 0) {
                wbb[tok * 16 + w] = b;
                wbb2[tok * 16 + w] = b2;
                wbi[tok * 16 + w] = bi;
            }
        }
        __syncthreads();

        // ---- final reduce + rescue + epilogue: one thread per token ----
        if (tid < TB) {
            int t = base + tid;
            if (t < N) {
                float b = 3.4e38f, b2 = 3.4e38f;
                int bi = 0;
#pragma unroll
                for (int k = 0; k < 16; k++) {
                    float vb  = wbb[tid * 16 + k];
                    float vb2 = wbb2[tid * 16 + k];
                    int   vi  = wbi[tid * 16 + k];
                    if (vb < b) { b2 = fminf(b, vb2); b = vb; bi = vi; }
                    else        { b2 = fminf(b2, vb); }
                }
                int bidx = bi;
                const unsigned long long* z2t = zb + tid * 32;

                if (b2 - b < 1e-4f) {
                    // ---- bit-frozen RESCUE (reference-replica d2 + tie-force) ----
                    float zz_;
                    GPU_SUMSQ64(GZ_T, zz_);
                    float bestr_ = 3.4e38f, bestr2_ = 3.4e38f;
                    int bir_ = 0, bir2_ = 0;
                    for (int c_ = 0; c_ < CBN; c_++) {
                        const float* p_ = cb + c_ * LAT;
                        float a_ = 0.f;
#pragma unroll
                        for (int d_ = 0; d_ < LAT; d_++)
                            a_ = fmaf(GZ_T(d_), p_[d_], a_);
                        float t0_ = zz_ - 2.f * a_;
                        float sc_ = t0_ + g_cbnorm[c_];
                        if (sc_ < bestr_) { bestr2_ = bestr_; bir2_ = bir_; bestr_ = sc_; bir_ = c_; }
                        else if (sc_ < bestr2_) { bestr2_ = sc_; bir2_ = c_; }
                    }
                    bidx = bir_;
                    float win_ = fabsf(bestr_) * 2.4e-7f;
                    if (bestr2_ - bestr_ <= win_ && bir2_ < bir_) bidx = bir2_;
                }

                // ---- bit-frozen EPILOGUE (exact commit d2, rec/idx writes) ----
                float d2_ = 0.f;
                const float* cr_ = cb + bidx * LAT;
#pragma unroll
                for (int u_ = 0; u_ < 32; u_++) {
                    unsigned long long zz2_ = z2t[u_];
                    float zl_ = __uint_as_float((unsigned int)zz2_);
                    float zh_ = __uint_as_float((unsigned int)(zz2_ >> 32));
                    float dl_ = zl_ - cr_[2 * u_];
                    float dh_ = zh_ - cr_[2 * u_ + 1];
                    d2_ = fmaf(dl_, dl_, d2_);
                    d2_ = fmaf(dh_, dh_, d2_);
                }
                atomicAdd(&hs[bidx], 1);
                atomicAdd(&csum, __float2ull_rn(d2_ * 4194304.f));
                if (out_idx) out_idx[t] = (float)bidx;
                if (out_rec) {
                    float* orp_ = out_rec + (size_t)t * NIN;
                    const float* tb_ = g_table + bidx * 16;
#pragma unroll
                    for (int i_ = 0; i_ < NIN; i_++)
                        orp_[i_] = __ldg(&tb_[i_]);
                }
            }
        }
        __syncthreads();
    }

    int v = hs[tid];
    if (v) atomicAdd(&g_hist[tid], v);
    if (tid == 0) atomicAdd(&g_commit, csum);
}

// ---------------- kernel 4: finalize scalars ----------------
__global__ void k_fin(float* out_commit, float* out_perp, int N) {
    __shared__ float red[512];
    int tid = threadIdx.x;
    float p = (float)g_hist[tid] / (float)N;
    red[tid] = p * logf(p + 1e-10f);
    __syncthreads();
    for (int s = 256; s; s >>= 1) {
        if (tid < s) red[tid] += red[tid + s];
        __syncthreads();
    }
    if (tid == 0) {
        if (out_perp) *out_perp = expf(-red[0]);
        if (out_commit) {
            double sum = (double)g_commit * (1.0 / 4194304.0);
            *out_commit = (float)(0.25 * sum / ((double)N * 64.0));
        }
    }
}

// ---------------- launch ----------------
extern "C" void kernel_launch(void* const* d_in, const int* in_sizes, int n_in,
                              void* d_out, int out_size) {
    (void)n_in;
    const float* x   = (const float*)d_in[0];
    const float* ew1 = (const float*)d_in[1];
    const float* eb1 = (const float*)d_in[2];
    const float* l1g = (const float*)d_in[3];
    const float* l1b = (const float*)d_in[4];
    const float* ew2 = (const float*)d_in[5];
    const float* eb2 = (const float*)d_in[6];
    const float* cbk = (const float*)d_in[7];
    const float* dw1 = (const float*)d_in[8];
    const float* db1 = (const float*)d_in[9];
    const float* l2g = (const float*)d_in[10];
    const float* l2b = (const float*)d_in[11];
    const float* dw2 = (const float*)d_in[12];
    const float* db2 = (const float*)d_in[13];

    int N = in_sizes[0] / NIN;
    if (N > MAXN) N = MAXN;

    float* out = (float*)d_out;
    long long rec_n = (long long)N * NIN;
    long long osz = (long long)out_size;
    float* out_rec    = (osz >= rec_n)             ? out : nullptr;
    float* out_idx    = (osz >= rec_n + N)         ? out + rec_n : nullptr;
    float* out_commit = (osz >= rec_n + N + 1)     ? out + rec_n + N : nullptr;
    float* out_perp   = (osz >= rec_n + N + 2)     ? out + rec_n + N + 1 : nullptr;

    k_init<<<1, 512>>>();
    k_dectab<<<CBN / 8, 256>>>(cbk, dw1, db1, l2g, l2b, dw2, db2);

    int smem_enc = (NIN * HID + HID * LAT) * 4 + 8 * 4 * HID * 8;  // 72704 B
    cudaFuncSetAttribute(k_enc, cudaFuncAttributeMaxDynamicSharedMemorySize, smem_enc);
    k_enc<<<444, 256, smem_enc>>>(x, ew1, eb1, l1g, l1b, ew2, eb2, N);

    // zb 32KB + winners (TB*16*(4+4+4)) 24KB + hist 2KB
    int smem_vq = TB * 32 * 8 + TB * 16 * 12 + CBN * 4;  // 59392 B
    cudaFuncSetAttribute(k_vq, cudaFuncAttributeMaxDynamicSharedMemorySize, smem_vq);
    k_vq<<<148, 512, smem_vq>>>(cbk, out_rec, out_idx, N);

    k_fin<<<1, 512>>>(out_commit, out_perp, N);
}

// round 12
// speedup vs baseline: 2.6746x; 2.6746x over previous
// R12: resubmission of R11 (bench infra failure "Trio nursery" — no kernel diagnostic).
#include <cuda_runtime.h>
#include <math.h>

#define NIN 14
#define HID 128
#define LAT 64
#define CBN 512
#define MAXN 131072

#define SQRT2_F 1.41421356237f

// ---------------- device scratch (static: no allocations allowed) ----------------
__device__ unsigned long long g_zbuf[(size_t)MAXN * 32];  // z as f32x2 pairs, 33.5MB
__device__ float g_table[CBN * 16];                       // precomputed decoder outputs
__device__ float g_cbnorm[CBN];                           // sum(c*c), XLA:GPU warp-tree order
__device__ int g_hist[CBN];
__device__ unsigned long long g_commit;                   // fixed-point sum of ||q-z||^2

// ---------------- packed f32x2 helpers ----------------
static __device__ __forceinline__ unsigned long long ffma2(unsigned long long a,
                                                           unsigned long long b,
                                                           unsigned long long c) {
    unsigned long long d;
    asm("fma.rn.f32x2 %0, %1, %2, %3;" : "=l"(d) : "l"(a), "l"(b), "l"(c));
    return d;
}
static __device__ __forceinline__ unsigned long long fadd2(unsigned long long a,
                                                           unsigned long long b) {
    unsigned long long d;
    asm("add.rn.f32x2 %0, %1, %2;" : "=l"(d) : "l"(a), "l"(b));
    return d;
}
static __device__ __forceinline__ unsigned long long pack2(float lo, float hi) {
    unsigned long long r;
    asm("mov.b64 %0, {%1, %2};" : "=l"(r) : "r"(__float_as_uint(lo)), "r"(__float_as_uint(hi)));
    return r;
}
static __device__ __forceinline__ float2 unpack2(unsigned long long v) {
    unsigned int lo, hi;
    asm("mov.b64 {%0, %1}, %2;" : "=r"(lo), "=r"(hi) : "l"(v));
    float2 r;
    r.x = __uint_as_float(lo);
    r.y = __uint_as_float(hi);
    return r;
}

// reference-style GELU: 0.5 * x * (1 + erf(x / sqrt(2)))
static __device__ __forceinline__ float gelu_ref(float v) {
    float e = erff(v / SQRT2_F);
    return (v * (e + 1.f)) * 0.5f;
}

// XLA:GPU row-reduction emulation for 64-wide sum-of-squares (bit-frozen from R7).
#define GPU_SUMSQ64(getv, result) do {                                        \
    float _a[32];                                                             \
    _Pragma("unroll") for (int _t = 0; _t < 32; _t++) {                       \
        float _v0 = getv(_t);                                                 \
        float _v1 = getv(_t + 32);                                            \
        _a[_t] = fmaf(_v1, _v1, _v0 * _v0);                                   \
    }                                                                         \
    _Pragma("unroll") for (int _o = 16; _o >= 1; _o >>= 1)                    \
    _Pragma("unroll") for (int _t = 0; _t < 16; _t++)                         \
        if (_t < _o) _a[_t] = _a[_t] + _a[_t + _o];                           \
    result = _a[0];                                                           \
} while (0)

// ---------------- kernel 0: zero the cross-launch scratch ----------------
__global__ void k_init() {
    int t = threadIdx.x;
    if (t < CBN) g_hist[t] = 0;
    if (t == 0) g_commit = 0ULL;
}

// ---------------- kernel 1: decoder table (unchanged, bit-frozen) ----------
__global__ __launch_bounds__(256) void k_dectab(
    const float* __restrict__ cb,
    const float* __restrict__ w1, const float* __restrict__ b1,
    const float* __restrict__ g1, const float* __restrict__ bt1,
    const float* __restrict__ w2, const float* __restrict__ b2)
{
    __shared__ float w1s[LAT * HID];
    __shared__ float w2s[HID * NIN];
    __shared__ float cbuf[8][LAT];
    __shared__ float gbuf[8][HID];
    int tid = threadIdx.x;
    for (int i = tid; i < LAT * HID; i += 256) w1s[i] = w1[i];
    for (int i = tid; i < HID * NIN; i += 256) w2s[i] = w2[i];
    __syncthreads();

    int lane = tid & 31, w = tid >> 5;
    int c = blockIdx.x * 8 + w;

    for (int d = lane; d < LAT; d += 32) cbuf[w][d] = __ldg(&cb[c * LAT + d]);
    __syncwarp();

    if (lane == 0) {
        float ns;
#define GETC(d) (cbuf[w][(d)])
        GPU_SUMSQ64(GETC, ns);
#undef GETC
        g_cbnorm[c] = ns;
    }

    float h[4];
#pragma unroll
    for (int u = 0; u < 4; u++) {
        int j = u * 32 + lane;
        float acc = 0.f;
        for (int d = 0; d < LAT; d++) acc = fmaf(cbuf[w][d], w1s[d * HID + j], acc);
        h[u] = acc + __ldg(&b1[j]);
    }
    float s = (h[0] + h[1]) + (h[2] + h[3]);
#pragma unroll
    for (int o = 16; o; o >>= 1) s += __shfl_xor_sync(~0u, s, o);
    float mean = s * (1.f / HID);
    float dv[4], s2 = 0.f;
#pragma unroll
    for (int u = 0; u < 4; u++) { dv[u] = h[u] - mean; float sq = dv[u] * dv[u]; s2 = s2 + sq; }
#pragma unroll
    for (int o = 16; o; o >>= 1) s2 += __shfl_xor_sync(~0u, s2, o);
    float var = s2 * (1.f / HID);
    float rstd = 1.f / sqrtf(var + 1e-5f);
#pragma unroll
    for (int u = 0; u < 4; u++) {
        int j = u * 32 + lane;
        float t = dv[u] * rstd;
        float t2 = t * __ldg(&g1[j]);
        float v = t2 + __ldg(&bt1[j]);
        gbuf[w][j] = gelu_ref(v);
    }
    __syncwarp();
    if (lane < NIN) {
        float acc = 0.f;
        for (int j = 0; j < HID; j++) acc = fmaf(gbuf[w][j], w2s[j * NIN + lane], acc);
        g_table[c * 16 + lane] = acc + __ldg(&b2[lane]);
    }
}

// ---------------- kernel 2: encoder, 8 tokens/warp, interleaved w2 ----------
// Per-token arithmetic is bit-identical to R7-R9: same enc1 chain, LN shuffles,
// gelu, and enc2 sequential j=0..127 chain acc=ffma2(dup(g[j]), w2pair[j], acc)
// with bias added after. Only operand DELIVERY changed: w2 in an interleaved
// (j,j+1)-paired layout read via one LDS.128 per 2 j's, g as plain floats read
// via broadcast LDS.64 per 2 j's, duplicated with pack2 (ALU pipe).
__global__ __launch_bounds__(256) void k_enc(
    const float* __restrict__ x,
    const float* __restrict__ w1, const float* __restrict__ b1,
    const float* __restrict__ g1, const float* __restrict__ bt1,
    const float* __restrict__ w2, const float* __restrict__ b2, int N)
{
    extern __shared__ float esm[];
    float* w1s = esm;                          // NIN*HID = 1792 floats (7KB)
    float* w2i = w1s + NIN * HID;              // interleaved w2: 8192 floats (32KB)
    float* gsf = w2i + HID * LAT;              // g floats: 8 warps * 8 tok * HID (32KB)

    int tid = threadIdx.x;
    for (int i = tid; i < NIN * HID; i += 256) w1s[i] = w1[i];
    // interleaved layout: w2i[(j/2)*128 + l*4 + {0,1,2,3}] =
    //   { w2[j][2l], w2[j][2l+1], w2[j+1][2l], w2[j+1][2l+1] }
    for (int i = tid; i < HID * LAT; i += 256) {
        int jp = i >> 7;            // j/2
        int r = i & 127;
        int l = r >> 2;
        int comp = r & 3;
        int j = 2 * jp + (comp >> 1);
        int d = 2 * l + (comp & 1);
        w2i[i] = w2[j * LAT + d];
    }
    __syncthreads();

    int lane = tid & 31, w = tid >> 5;

    float b1v[4], g1v[4], btv[4];
#pragma unroll
    for (int u = 0; u < 4; u++) {
        int j = u * 32 + lane;
        b1v[u] = __ldg(&b1[j]);
        g1v[u] = __ldg(&g1[j]);
        btv[u] = __ldg(&bt1[j]);
    }
    unsigned long long b2p = pack2(__ldg(&b2[2 * lane]), __ldg(&b2[2 * lane + 1]));

    int gw = blockIdx.x * 8 + w;
    int nw = gridDim.x * 8;

    for (int t0 = gw * 8; t0 < N; t0 += nw * 8) {
        // ---- front phase: enc1 + LN + GELU for 8 tokens (bit-frozen order) ----
#pragma unroll 1
        for (int m = 0; m < 8; m++) {
            int t = t0 + m;
            float gl0 = 0.f, gl1 = 0.f, gl2 = 0.f, gl3 = 0.f;
            if (t < N) {
                const float* xp = x + (size_t)t * NIN;
                float xv[NIN];
#pragma unroll
                for (int i = 0; i < NIN; i++) xv[i] = __ldg(&xp[i]);
                float h[4];
#pragma unroll
                for (int u = 0; u < 4; u++) {
                    float acc = 0.f;
#pragma unroll
                    for (int i = 0; i < NIN; i++) acc = fmaf(xv[i], w1s[i * HID + u * 32 + lane], acc);
                    h[u] = acc + b1v[u];
                }
                float s = (h[0] + h[1]) + (h[2] + h[3]);
#pragma unroll
                for (int o = 16; o; o >>= 1) s += __shfl_xor_sync(~0u, s, o);
                float mean = s * (1.f / HID);
                float dv[4], s2 = 0.f;
#pragma unroll
                for (int u = 0; u < 4; u++) { dv[u] = h[u] - mean; float sq = dv[u] * dv[u]; s2 = s2 + sq; }
#pragma unroll
                for (int o = 16; o; o >>= 1) s2 += __shfl_xor_sync(~0u, s2, o);
                float var = s2 * (1.f / HID);
                float rstd = 1.f / sqrtf(var + 1e-5f);
                float t1, t2, v;
                t1 = dv[0] * rstd; t2 = t1 * g1v[0]; v = t2 + btv[0]; gl0 = gelu_ref(v);
                t1 = dv[1] * rstd; t2 = t1 * g1v[1]; v = t2 + btv[1]; gl1 = gelu_ref(v);
                t1 = dv[2] * rstd; t2 = t1 * g1v[2]; v = t2 + btv[2]; gl2 = gelu_ref(v);
                t1 = dv[3] * rstd; t2 = t1 * g1v[3]; v = t2 + btv[3]; gl3 = gelu_ref(v);
            }
            float* gp = gsf + (w * 8 + m) * HID;
            gp[0 * 32 + lane] = gl0;
            gp[1 * 32 + lane] = gl1;
            gp[2 * 32 + lane] = gl2;
            gp[3 * 32 + lane] = gl3;
        }
        __syncwarp();

        // ---- enc2: sequential j-chain per token; one w2 read serves 8 tokens ----
        unsigned long long acc[8];
#pragma unroll
        for (int m = 0; m < 8; m++) acc[m] = 0ULL;
        const float* g0 = gsf + (w * 8) * HID;
#pragma unroll 4
        for (int j = 0; j < HID; j += 2) {
            // 16B per lane: packed pairs for (j, j+1) at this lane's two dims
            ulonglong2 wv = *(const ulonglong2*)&w2i[(j >> 1) * 128 + lane * 4];
#pragma unroll
            for (int m = 0; m < 8; m++) {
                float2 g2 = *(const float2*)&g0[m * HID + j];   // broadcast LDS.64
                acc[m] = ffma2(pack2(g2.x, g2.x), wv.x, acc[m]);
                acc[m] = ffma2(pack2(g2.y, g2.y), wv.y, acc[m]);
            }
        }
        __syncwarp();
#pragma unroll
        for (int m = 0; m < 8; m++) {
            int t = t0 + m;
            if (t < N) g_zbuf[(size_t)t * 32 + lane] = fadd2(acc[m], b2p);
        }
    }
}

// ---------------- kernel 3: VQ, 2 tokens/thread, software-pipelined (R9 exact) --
#define GZ_ARR(arr, d) (((d) & 1) ? __uint_as_float((unsigned int)((arr)[(d) >> 1] >> 32)) \
                                  : __uint_as_float((unsigned int)(arr)[(d) >> 1]))
#define GZ_A(d) GZ_ARR(z2a, d)
#define GZ_B(d) GZ_ARR(z2b, d)

// Rescue (bit-frozen from R7): reference-replica d2 + quantization-tie force.
#define RESCUE(GETV, BIDXVAR) do {                                            \
    float zz_;                                                                \
    GPU_SUMSQ64(GETV, zz_);                                                   \
    float bestr_ = 3.4e38f, bestr2_ = 3.4e38f;                                \
    int bir_ = 0, bir2_ = 0;                                                  \
    for (int c_ = 0; c_ < CBN; c_++) {                                        \
        const float* p_ = cbs + c_ * LAT;                                     \
        float a_ = 0.f;                                                       \
        _Pragma("unroll") for (int d_ = 0; d_ < LAT; d_++)                    \
            a_ = fmaf(GETV(d_), p_[d_], a_);                                  \
        float t0_ = zz_ - 2.f * a_;                                           \
        float sc_ = t0_ + cns[c_];                                            \
        if (sc_ < bestr_) { bestr2_ = bestr_; bir2_ = bir_; bestr_ = sc_; bir_ = c_; } \
        else if (sc_ < bestr2_) { bestr2_ = sc_; bir2_ = c_; }                \
    }                                                                         \
    BIDXVAR = bir_;                                                           \
    float win_ = fabsf(bestr_) * 2.4e-7f;                                     \
    if (bestr2_ - bestr_ <= win_ && bir2_ < bir_) BIDXVAR = bir2_;            \
} while (0)

#define EPILOGUE(ARR, BIDX, T) do {                                           \
    float d2_ = 0.f;                                                          \
    const float* cr_ = cbs + (BIDX) * LAT;                                    \
    _Pragma("unroll") for (int u_ = 0; u_ < 32; u_++) {                       \
        unsigned long long zz2_ = (ARR)[u_];                                  \
        float zl_ = __uint_as_float((unsigned int)zz2_);                      \
        float zh_ = __uint_as_float((unsigned int)(zz2_ >> 32));              \
        float dl_ = zl_ - cr_[2 * u_];                                        \
        float dh_ = zh_ - cr_[2 * u_ + 1];                                    \
        d2_ = fmaf(dl_, dl_, d2_);                                            \
        d2_ = fmaf(dh_, dh_, d2_);                                            \
    }                                                                         \
    atomicAdd(&hs[BIDX], 1);                                                  \
    atomicAdd(&csum, __float2ull_rn(d2_ * 4194304.f));                        \
    if (out_idx) out_idx[T] = (float)(BIDX);                                  \
    if (out_rec) {                                                            \
        float* orp_ = out_rec + (size_t)(T) * NIN;                            \
        const float* tb_ = g_table + (BIDX) * 16;                             \
        _Pragma("unroll") for (int i_ = 0; i_ < NIN; i_++)                    \
            orp_[i_] = __ldg(&tb_[i_]);                                       \
    }                                                                         \
} while (0)

__global__ __launch_bounds__(256) void k_vq(
    const float* __restrict__ cb,
    float* __restrict__ out_rec, float* __restrict__ out_idx, int N)
{
    extern __shared__ float sm[];
    float* cbs = sm;                        // 512*64 floats = 128KB
    float* cns = sm + CBN * LAT;            // 512 floats
    int* hs = (int*)(cns + CBN);            // 512 ints
    __shared__ unsigned long long csum;

    int tid = threadIdx.x;
    for (int i = tid; i < CBN * LAT; i += 256) cbs[i] = cb[i];
    for (int i = tid; i < CBN; i += 256) { cns[i] = g_cbnorm[i]; hs[i] = 0; }
    if (tid == 0) csum = 0ULL;
    __syncthreads();

    for (int base = blockIdx.x * 512; base < N; base += gridDim.x * 512) {
        int ta = base + tid;
        int tb = base + 256 + tid;
        bool va = ta < N, vb = tb < N;
        int la = va ? ta : 0;
        int lb = vb ? tb : la;

        unsigned long long z2a[32], z2b[32];
        {
            const ulonglong2* zp = (const ulonglong2*)&g_zbuf[(size_t)la * 32];
#pragma unroll
            for (int u = 0; u < 16; u++) {
                ulonglong2 v = zp[u];
                z2a[2 * u] = v.x;
                z2a[2 * u + 1] = v.y;
            }
        }
        {
            const ulonglong2* zp = (const ulonglong2*)&g_zbuf[(size_t)lb * 32];
#pragma unroll
            for (int u = 0; u < 16; u++) {
                ulonglong2 v = zp[u];
                z2b[2 * u] = v.x;
                z2b[2 * u + 1] = v.y;
            }
        }

        float bestA = 3.4e38f, best2A = 3.4e38f, bestB = 3.4e38f, best2B = 3.4e38f;
        int bidxA = 0, bidxB = 0;
        ulonglong2 bh0[8], bh1[8];
        {
            const ulonglong2* cp = (const ulonglong2*)cbs;
#pragma unroll
            for (int i = 0; i < 8; i++) bh0[i] = cp[i];
        }
#pragma unroll 1
        for (int c = 0; c < CBN; c++) {
            const ulonglong2* cp = (const ulonglong2*)(cbs + c * LAT);
#pragma unroll
            for (int i = 0; i < 8; i++) bh1[i] = cp[8 + i];
            unsigned long long aA0 = 0ULL, aA1 = 0ULL, aB0 = 0ULL, aB1 = 0ULL;
#pragma unroll
            for (int u = 0; u < 4; u++) {
                aA0 = ffma2(z2a[4 * u + 0], bh0[2 * u].x, aA0);
                aA1 = ffma2(z2a[4 * u + 1], bh0[2 * u].y, aA1);
                aA0 = ffma2(z2a[4 * u + 2], bh0[2 * u + 1].x, aA0);
                aA1 = ffma2(z2a[4 * u + 3], bh0[2 * u + 1].y, aA1);
                aB0 = ffma2(z2b[4 * u + 0], bh0[2 * u].x, aB0);
                aB1 = ffma2(z2b[4 * u + 1], bh0[2 * u].y, aB1);
                aB0 = ffma2(z2b[4 * u + 2], bh0[2 * u + 1].x, aB0);
                aB1 = ffma2(z2b[4 * u + 3], bh0[2 * u + 1].y, aB1);
            }
            {
                const ulonglong2* cpn = (const ulonglong2*)(cbs + ((c + 1) & (CBN - 1)) * LAT);
#pragma unroll
                for (int i = 0; i < 8; i++) bh0[i] = cpn[i];
            }
#pragma unroll
            for (int u = 0; u < 4; u++) {
                aA0 = ffma2(z2a[16 + 4 * u + 0], bh1[2 * u].x, aA0);
                aA1 = ffma2(z2a[16 + 4 * u + 1], bh1[2 * u].y, aA1);
                aA0 = ffma2(z2a[16 + 4 * u + 2], bh1[2 * u + 1].x, aA0);
                aA1 = ffma2(z2a[16 + 4 * u + 3], bh1[2 * u + 1].y, aA1);
                aB0 = ffma2(z2b[16 + 4 * u + 0], bh1[2 * u].x, aB0);
                aB1 = ffma2(z2b[16 + 4 * u + 1], bh1[2 * u].y, aB1);
                aB0 = ffma2(z2b[16 + 4 * u + 2], bh1[2 * u + 1].x, aB0);
                aB1 = ffma2(z2b[16 + 4 * u + 3], bh1[2 * u + 1].y, aB1);
            }
            float cn = cns[c];
            float2 fA = unpack2(fadd2(aA0, aA1));
            float scoreA = fmaf(-2.f, fA.x + fA.y, cn);
            if (scoreA < bestA) { best2A = bestA; bestA = scoreA; bidxA = c; }
            else if (scoreA < best2A) { best2A = scoreA; }
            float2 fB = unpack2(fadd2(aB0, aB1));
            float scoreB = fmaf(-2.f, fB.x + fB.y, cn);
            if (scoreB < bestB) { best2B = bestB; bestB = scoreB; bidxB = c; }
            else if (scoreB < best2B) { best2B = scoreB; }
        }

        if (best2A - bestA < 1e-4f) RESCUE(GZ_A, bidxA);
        if (best2B - bestB < 1e-4f) RESCUE(GZ_B, bidxB);

        if (va) EPILOGUE(z2a, bidxA, ta);
        if (vb) EPILOGUE(z2b, bidxB, tb);
    }
    __syncthreads();
    for (int i = tid; i < CBN; i += 256) {
        int v = hs[i];
        if (v) atomicAdd(&g_hist[i], v);
    }
    if (tid == 0) atomicAdd(&g_commit, csum);
}

// ---------------- kernel 4: finalize scalars ----------------
__global__ void k_fin(float* out_commit, float* out_perp, int N) {
    __shared__ float red[512];
    int tid = threadIdx.x;
    float p = (float)g_hist[tid] / (float)N;
    red[tid] = p * logf(p + 1e-10f);
    __syncthreads();
    for (int s = 256; s; s >>= 1) {
        if (tid < s) red[tid] += red[tid + s];
        __syncthreads();
    }
    if (tid == 0) {
        if (out_perp) *out_perp = expf(-red[0]);
        if (out_commit) {
            double sum = (double)g_commit * (1.0 / 4194304.0);
            *out_commit = (float)(0.25 * sum / ((double)N * 64.0));
        }
    }
}

// ---------------- launch ----------------
extern "C" void kernel_launch(void* const* d_in, const int* in_sizes, int n_in,
                              void* d_out, int out_size) {
    (void)n_in;
    const float* x   = (const float*)d_in[0];
    const float* ew1 = (const float*)d_in[1];
    const float* eb1 = (const float*)d_in[2];
    const float* l1g = (const float*)d_in[3];
    const float* l1b = (const float*)d_in[4];
    const float* ew2 = (const float*)d_in[5];
    const float* eb2 = (const float*)d_in[6];
    const float* cbk = (const float*)d_in[7];
    const float* dw1 = (const float*)d_in[8];
    const float* db1 = (const float*)d_in[9];
    const float* l2g = (const float*)d_in[10];
    const float* l2b = (const float*)d_in[11];
    const float* dw2 = (const float*)d_in[12];
    const float* db2 = (const float*)d_in[13];

    int N = in_sizes[0] / NIN;
    if (N > MAXN) N = MAXN;

    float* out = (float*)d_out;
    long long rec_n = (long long)N * NIN;
    long long osz = (long long)out_size;
    float* out_rec    = (osz >= rec_n)             ? out : nullptr;
    float* out_idx    = (osz >= rec_n + N)         ? out + rec_n : nullptr;
    float* out_commit = (osz >= rec_n + N + 1)     ? out + rec_n + N : nullptr;
    float* out_perp   = (osz >= rec_n + N + 2)     ? out + rec_n + N + 1 : nullptr;

    k_init<<<1, 512>>>();
    k_dectab<<<CBN / 8, 256>>>(cbk, dw1, db1, l2g, l2b, dw2, db2);

    // w1s 7KB + w2i 32KB + gsf 32KB = 71KB -> 3 blocks/SM
    int smem_enc = (NIN * HID + HID * LAT + 8 * 8 * HID) * 4;  // 72704 B
    cudaFuncSetAttribute(k_enc, cudaFuncAttributeMaxDynamicSharedMemorySize, smem_enc);
    k_enc<<<444, 256, smem_enc>>>(x, ew1, eb1, l1g, l1b, ew2, eb2, N);

    int smem = CBN * LAT * 4 + CBN * 4 + CBN * 4;  // 135168 B
    cudaFuncSetAttribute(k_vq, cudaFuncAttributeMaxDynamicSharedMemorySize, smem);
    k_vq<<<148, 256, smem>>>(cbk, out_rec, out_idx, N);

    k_fin<<<1, 512>>>(out_commit, out_perp, N);
}